// round 12
// baseline (speedup 1.0000x reference)
#include <cuda_runtime.h>

// Problem constants
#define BB   64      // batch
#define L0   128     // input length
#define C0   16      // input channels
#define L1C  124     // len after block1
#define CH1  128     // channels after block1
#define CH2  1024    // channels after block2
#define L3C  116     // len after block3
#define CH3  8192    // channels after block3

#define NSLICE 16
#define LCHUNK 29
#define NLC 4                            // 4 x 29 = 116 exactly
#define ZB  2                            // 16 batch pairs per block
#define CTILES 128                       // 8 channels per tile
#define FUSED_BLOCKS (CTILES * NLC * ZB) // 1024
#define SPAN 33                          // x2 l-span per block = LCHUNK + 4
#define SPAN_PAD 34                      // row = 272B
#define OSPAN 37                         // out1 l-span

// Dynamic smem partition (ull units)
#define X2S_ULL (16 * 8 * SPAN_PAD)      // 4352 ull = 34816 B
#define WS_ULL  (LCHUNK * 64)            // 1856 ull = 14848 B
#define O1S_ULL (16 * 40)                //  640 ull =  5120 B
#define SMEM_BYTES ((X2S_ULL + WS_ULL + O1S_ULL) * 8)   // 54784 B

typedef unsigned long long ull;

// Scratch (device globals; no runtime allocation allowed)
__device__ ull   g_out1p[(BB / 2) * L1C * CH1]; // [bpair][l][o], packed batches
__device__ float g_acc [NSLICE][BB * 2];        // sliced dense accumulators
__device__ unsigned g_count;                    // completed-block counter

// ---------------------------------------------------------------------------
// Packed f32x2 helpers (sm_103a FFMA2 — PTX-only)
__device__ __forceinline__ ull pack2(float lo, float hi) {
    ull d; asm("mov.b64 %0, {%1, %2};" : "=l"(d) : "f"(lo), "f"(hi));
    return d;
}
__device__ __forceinline__ void unpack2(ull d, float& lo, float& hi) {
    asm("mov.b64 {%0, %1}, %2;" : "=f"(lo), "=f"(hi) : "l"(d));
}
__device__ __forceinline__ ull dup2(float v) {
    ull d; asm("mov.b64 %0, {%1, %1};" : "=l"(d) : "f"(v));
    return d;
}
__device__ __forceinline__ ull fma2(ull a, ull b, ull c) {
    ull d; asm("fma.rn.f32x2 %0, %1, %2, %3;" : "=l"(d) : "l"(a), "l"(b), "l"(c));
    return d;
}
__device__ __forceinline__ ull relu2(ull x) {
    float lo, hi; unpack2(x, lo, hi);
    return pack2(fmaxf(lo, 0.f), fmaxf(hi, 0.f));
}

// ---------------------------------------------------------------------------
// Block1 (+ zero accumulators/counter). out1 packed by batch pair,
// layout [bp][l][o]. (Round-8 version — broadcast state reads, coalesced writes.)
__global__ void block1_kernel(const float* __restrict__ state,
                              const float* __restrict__ k1w,
                              const float* __restrict__ b1) {
    int idx = blockIdx.x * blockDim.x + threadIdx.x;
    if (idx < NSLICE * BB * 2) ((float*)g_acc)[idx] = 0.f;
    if (idx == 0) g_count = 0u;
    if (idx >= BB * L1C * CH1) return;
    int o = idx & (CH1 - 1);
    int l = (idx >> 7) % L1C;
    int b = idx / (L1C * CH1);
    int c = o >> 3;
    const float* sp = state + (b * L0 + l) * C0 + c;
    float v = b1[o];
#pragma unroll
    for (int k = 0; k < 5; k++) v = fmaf(sp[k * C0], k1w[k * CH1 + o], v);
    ((float*)g_out1p)[((size_t)(((b >> 1) * L1C + l) * CH1 + o) << 1) + (b & 1)] =
        fmaxf(v, 0.f);
}

// ---------------------------------------------------------------------------
// One l-point for 4 batch pairs. W scalars dup'd ONCE, shared by all pairs.
__device__ __forceinline__ void do_l4(int i, const ull xw[4][6],
                                      const ull w3p[5][2], const ull bias3p[2],
                                      ull u0, ull u1,
                                      ull accC0[4], ull accC1[4]) {
    float f0c0, f0c1, f1c0, f1c1;
    unpack2(u0, f0c0, f0c1);
    unpack2(u1, f1c0, f1c1);
    ull d00 = dup2(f0c0), d01 = dup2(f0c1);
    ull d10 = dup2(f1c0), d11 = dup2(f1c1);
#pragma unroll
    for (int p = 0; p < 4; p++) {
        ull v0 = bias3p[0], v1 = bias3p[1];
#pragma unroll
        for (int k = 0; k < 5; k++) {
            v0 = fma2(xw[p][(i + k) % 6], w3p[k][0], v0);
            v1 = fma2(xw[p][(i + k) % 6], w3p[k][1], v1);
        }
        v0 = relu2(v0);
        v1 = relu2(v1);
        accC0[p] = fma2(v0, d00, accC0[p]);
        accC1[p] = fma2(v0, d01, accC1[p]);
        accC0[p] = fma2(v1, d10, accC0[p]);
        accC1[p] = fma2(v1, d11, accC1[p]);
    }
}

// ---------------------------------------------------------------------------
// Fused block2 + block3 + dense + (last block) finalize. 128 threads.
// Phase 1a: stage dense-W slice [29 l][512B] (coalesced LDG128) AND out1
//   slice o1s[16 bp][37 l] into smem; one __syncthreads.
// Phase 1b: fill x2 tile [16 bp][8 c][33 l] from o1s LDS broadcasts.
// Phase 2: warp wg -> batch pairs wg*4..wg*4+3 (8 batches/thread);
//   lane = (cl 0..7 channel, fq 0..3 -> 2 filters). Double-step l loop:
//   4 LDS128 x2 refills per 2 l, 1 LDS128 W quad per l shared over 4 pairs.
__global__ void __launch_bounds__(128, 4)
fused23_kernel(const float* __restrict__ k2w, const float* __restrict__ b2,
               const float* __restrict__ k3w, const float* __restrict__ b3,
               const float* __restrict__ W,   const float* __restrict__ bd,
               float* __restrict__ out) {
    extern __shared__ ull dsm[];
    ull* x2s = dsm;                      // [bp*8+c][SPAN_PAD]
    ull* Wsm = dsm + X2S_ULL;            // [l][64]  (512B per l)
    ull* o1s = dsm + X2S_ULL + WS_ULL;   // [bp][40]

    int t  = threadIdx.x;
    int ct = blockIdx.x;                 // c-tile == out1 channel
    int l0 = blockIdx.y * LCHUNK;
    int zb = blockIdx.z;                 // 0/1 -> batch pairs zb*16..+15

    // ---------------- Phase 1a: stage W + out1 ----------------
    {
        int wgs = t >> 5, ln = t & 31;
        const float4* Wg = (const float4*)W + (size_t)l0 * 4096 + ct * 32 + ln;
        float4* Ws4 = (float4*)Wsm;
#pragma unroll
        for (int l = wgs; l < LCHUNK; l += 4)
            Ws4[l * 32 + ln] = Wg[(size_t)l * 4096];

        int r = t >> 3, j = t & 7;
        const ull* base =
            g_out1p + ((size_t)(zb * 16 + r) * L1C + l0) * CH1 + ct;
#pragma unroll
        for (int s = 0; s < 5; s++) {
            int i = j + 8 * s;
            if (i < OSPAN) o1s[r * 40 + i] = base[(size_t)i * CH1];
        }
    }
    __syncthreads();

    // ---------------- Phase 1b: fill x2 from smem ----------------
    {
        int fc  = t & 7;                 // channel in tile
        int fbp = t >> 3;                // batch pair 0..15
        int cF  = ct * 8 + fc;

        ull w2p[5];
#pragma unroll
        for (int k = 0; k < 5; k++) {
            float w = k2w[k * CH2 + cF]; w2p[k] = pack2(w, w);
        }
        float bv = b2[cF];
        ull bias2p = pack2(bv, bv);

        const ull* orow = &o1s[fbp * 40];
        ull w[5];
#pragma unroll
        for (int k = 0; k < 5; k++) w[k] = orow[k];
        ull* dst = &x2s[(fbp * 8 + fc) * SPAN_PAD];
#pragma unroll
        for (int i = 0; i < SPAN; i++) {
            ull v = bias2p;
#pragma unroll
            for (int k = 0; k < 5; k++) v = fma2(w[(i + k) % 5], w2p[k], v);
            dst[i] = relu2(v);
            if (i + 1 < SPAN) w[i % 5] = orow[i + 5];
        }
    }
    __syncthreads();

    // ---------------- Phase 2: conv3 + dense ----------------
    int cl = t & 7;                      // channel lane
    int fq = (t >> 3) & 3;               // filters fq*2, fq*2+1
    int wg = t >> 5;                     // warp -> pairs wg*4..wg*4+3
    int c  = ct * 8 + cl;

    ull w3p[5][2];
#pragma unroll
    for (int k = 0; k < 5; k++)
#pragma unroll
        for (int j = 0; j < 2; j++) {
            float w = k3w[k * CH3 + c * 8 + fq * 2 + j];
            w3p[k][j] = pack2(w, w);
        }
    ull bias3p[2];
#pragma unroll
    for (int j = 0; j < 2; j++) {
        float bv = b3[c * 8 + fq * 2 + j];
        bias3p[j] = pack2(bv, bv);
    }

    const ulonglong2* xsv[4];
#pragma unroll
    for (int p = 0; p < 4; p++)
        xsv[p] = (const ulonglong2*)&x2s[((wg * 4 + p) * 8 + cl) * SPAN_PAD];

    // W quad (f0c0,f0c1,f1c0,f1c1) at smem ulonglong2 index l*32 + cl*4 + fq
    const ulonglong2* Wsv = (const ulonglong2*)Wsm + cl * 4 + fq;

    ull xw[4][6];
#pragma unroll
    for (int p = 0; p < 4; p++) {
        ulonglong2 a = xsv[p][0], b_ = xsv[p][1], e = xsv[p][2];
        xw[p][0] = a.x; xw[p][1] = a.y; xw[p][2] = b_.x;
        xw[p][3] = b_.y; xw[p][4] = e.x; xw[p][5] = e.y;
    }

    ull accC0[4] = {}, accC1[4] = {};    // packed (b_even, b_odd) per pair

    ulonglong2 u = Wsv[0];
#pragma unroll
    for (int s = 0; s < 14; s++) {
        int i = 2 * s;
        ulonglong2 un1 = Wsv[(i + 1) * 32];
        ulonglong2 rf0 = xsv[0][(i + 6) >> 1];
        ulonglong2 rf1 = xsv[1][(i + 6) >> 1];
        do_l4(i, xw, w3p, bias3p, u.x, u.y, accC0, accC1);
        ulonglong2 un2 = Wsv[(i + 2) * 32];
        ulonglong2 rf2 = xsv[2][(i + 6) >> 1];
        ulonglong2 rf3 = xsv[3][(i + 6) >> 1];
        do_l4(i + 1, xw, w3p, bias3p, un1.x, un1.y, accC0, accC1);
        xw[0][i % 6] = rf0.x; xw[0][(i + 1) % 6] = rf0.y;
        xw[1][i % 6] = rf1.x; xw[1][(i + 1) % 6] = rf1.y;
        xw[2][i % 6] = rf2.x; xw[2][(i + 1) % 6] = rf2.y;
        xw[3][i % 6] = rf3.x; xw[3][(i + 1) % 6] = rf3.y;
        u = un2;
    }
    do_l4(28, xw, w3p, bias3p, u.x, u.y, accC0, accC1);  // final odd l

    // Warp reduction over 32 lanes (8 c x 4 fq) per pair / batch-half / col
    int sl = ct & (NSLICE - 1);
#pragma unroll
    for (int p = 0; p < 4; p++) {
        float se0, so0, se1, so1;
        unpack2(accC0[p], se0, so0);
        unpack2(accC1[p], se1, so1);
#pragma unroll
        for (int s = 16; s > 0; s >>= 1) {
            se0 += __shfl_xor_sync(0xFFFFFFFFu, se0, s);
            so0 += __shfl_xor_sync(0xFFFFFFFFu, so0, s);
            se1 += __shfl_xor_sync(0xFFFFFFFFu, se1, s);
            so1 += __shfl_xor_sync(0xFFFFFFFFu, so1, s);
        }
        if ((t & 31) == 0) {
            int be = (zb * 16 + wg * 4 + p) * 2;   // even batch of this pair
            atomicAdd(&g_acc[sl][be * 2],     se0);
            atomicAdd(&g_acc[sl][be * 2 + 1], se1);
            atomicAdd(&g_acc[sl][be * 2 + 2], so0);
            atomicAdd(&g_acc[sl][be * 2 + 3], so1);
        }
    }

    // Last block finalizes (threadfence reduction pattern)
    __shared__ bool s_last;
    __threadfence();
    __syncthreads();
    if (t == 0) s_last = (atomicAdd(&g_count, 1u) == FUSED_BLOCKS - 1u);
    __syncthreads();
    if (s_last) {
        __threadfence();
        int i = t;  // 128 threads == 128 outputs
        volatile float* ga = (volatile float*)g_acc;
        float v = 0.f;
#pragma unroll
        for (int s = 0; s < NSLICE; s++) v += ga[s * BB * 2 + i];
        out[i] = tanhf(v + bd[i & 1]);
    }
}

// ---------------------------------------------------------------------------
extern "C" void kernel_launch(void* const* d_in, const int* in_sizes, int n_in,
                              void* d_out, int out_size) {
    const float* state = (const float*)d_in[0];
    const float* k1w   = (const float*)d_in[1];
    const float* b1    = (const float*)d_in[2];
    const float* k2w   = (const float*)d_in[3];
    const float* b2    = (const float*)d_in[4];
    const float* k3w   = (const float*)d_in[5];
    const float* b3    = (const float*)d_in[6];
    const float* W     = (const float*)d_in[7];
    const float* bd    = (const float*)d_in[8];
    float* out = (float*)d_out;

    static bool attr_done = false;
    if (!attr_done) {
        cudaFuncSetAttribute(fused23_kernel,
                             cudaFuncAttributeMaxDynamicSharedMemorySize,
                             SMEM_BYTES);
        attr_done = true;
    }

    block1_kernel<<<(BB * L1C * CH1 + 255) / 256, 256>>>(state, k1w, b1);
    fused23_kernel<<<dim3(CTILES, NLC, ZB), 128, SMEM_BYTES>>>(
        k2w, b2, k3w, b3, W, bd, out);
}

// round 13
// speedup vs baseline: 1.1179x; 1.1179x over previous
#include <cuda_runtime.h>

// Problem constants
#define BB   64      // batch
#define L0   128     // input length
#define C0   16      // input channels
#define L1C  124     // len after block1
#define CH1  128     // channels after block1
#define CH2  1024    // channels after block2
#define L3C  116     // len after block3
#define CH3  8192    // channels after block3

#define NSLICE 16
#define LCHUNK 29
#define NLC 4                            // 4 x 29 = 116 exactly
#define ZB  2                            // 16 batch pairs per block
#define CTILES 128                       // 8 x2-channels per tile (== out1 ch)
#define FUSED_BLOCKS (CTILES * NLC * ZB) // 1024
#define SPAN 33                          // x2 l-span = LCHUNK + 4
#define SPAN_PAD 34
#define OSPAN 37                         // out1 l-span = SPAN + 4
#define SSPAN 41                         // state l-span = OSPAN + 4
#define SST_PITCH 44

typedef unsigned long long ull;

// Scratch (device globals; zero-initialized at load; kernel self-restores)
__device__ float g_acc[NSLICE][BB * 2];
__device__ unsigned g_count;

// ---------------------------------------------------------------------------
// Packed f32x2 helpers (sm_103a FFMA2 — PTX-only)
__device__ __forceinline__ ull pack2(float lo, float hi) {
    ull d; asm("mov.b64 %0, {%1, %2};" : "=l"(d) : "f"(lo), "f"(hi));
    return d;
}
__device__ __forceinline__ void unpack2(ull d, float& lo, float& hi) {
    asm("mov.b64 {%0, %1}, %2;" : "=f"(lo), "=f"(hi) : "l"(d));
}
__device__ __forceinline__ ull dup2(float v) {
    ull d; asm("mov.b64 %0, {%1, %1};" : "=l"(d) : "f"(v));
    return d;
}
__device__ __forceinline__ ull fma2(ull a, ull b, ull c) {
    ull d; asm("fma.rn.f32x2 %0, %1, %2, %3;" : "=l"(d) : "l"(a), "l"(b), "l"(c));
    return d;
}
__device__ __forceinline__ ull relu2(ull x) {
    float lo, hi; unpack2(x, lo, hi);
    return pack2(fmaxf(lo, 0.f), fmaxf(hi, 0.f));
}

// ---------------------------------------------------------------------------
// One l-point for 4 batch pairs. W scalars dup'd ONCE, shared by all pairs.
__device__ __forceinline__ void do_l4(int i, const ull xw[4][6],
                                      const ull w3p[5][2], const ull bias3p[2],
                                      ull u0, ull u1,
                                      ull accC0[4], ull accC1[4]) {
    float f0c0, f0c1, f1c0, f1c1;
    unpack2(u0, f0c0, f0c1);
    unpack2(u1, f1c0, f1c1);
    ull d00 = dup2(f0c0), d01 = dup2(f0c1);
    ull d10 = dup2(f1c0), d11 = dup2(f1c1);
#pragma unroll
    for (int p = 0; p < 4; p++) {
        ull v0 = bias3p[0], v1 = bias3p[1];
#pragma unroll
        for (int k = 0; k < 5; k++) {
            v0 = fma2(xw[p][(i + k) % 6], w3p[k][0], v0);
            v1 = fma2(xw[p][(i + k) % 6], w3p[k][1], v1);
        }
        v0 = relu2(v0);
        v1 = relu2(v1);
        accC0[p] = fma2(v0, d00, accC0[p]);
        accC1[p] = fma2(v0, d01, accC1[p]);
        accC0[p] = fma2(v1, d10, accC0[p]);
        accC1[p] = fma2(v1, d11, accC1[p]);
    }
}

// ---------------------------------------------------------------------------
// Single fully-fused kernel: block1 + block2 + block3 + dense + finalize.
// Grid (128 ct, 4 l-chunks, 2 zb), 128 threads.
// Phase 1a: stage state slice [32 b][41 l] of channel ct>>3 into smem.
// Phase 1b: block1 -> o1s[16 bp][37 l] (packed pairs) in smem.
// Phase 1c: block2 -> x2 tile [16 bp][8 c][33 l] in smem.
// Phase 2:  round-8 main loop: warp wg -> pairs wg*4..+3 (8 batches/thread),
//   lane = (cl 0..7 channel, fq 0..3 -> 2 filters); double-step l loop with
//   4 LDS128 x2 refills per 2 l + 1 LDG128 W quad per l (prefetched).
// Finalize: last block sums slices + bias + tanh, then SELF-RESTORES
//   g_acc/g_count to zero (each thread zeros exactly what it read).
__global__ void __launch_bounds__(128, 4)
fused_all_kernel(const float* __restrict__ state,
                 const float* __restrict__ k1w, const float* __restrict__ b1,
                 const float* __restrict__ k2w, const float* __restrict__ b2,
                 const float* __restrict__ k3w, const float* __restrict__ b3,
                 const float* __restrict__ W,   const float* __restrict__ bd,
                 float* __restrict__ out) {
    __shared__ ull   x2s[16 * 8 * SPAN_PAD];   // 34816 B
    __shared__ ull   o1s[16][40];              //  5120 B
    __shared__ float s_st[32][SST_PITCH];      //  5632 B   (45.6 KB total)

    int t  = threadIdx.x;
    int ct = blockIdx.x;                 // out1 channel 0..127
    int l0 = blockIdx.y * LCHUNK;
    int zb = blockIdx.z;                 // batches zb*32..zb*32+31

    // ---------------- Phase 1a: stage state slice ----------------
    {
        int bl  = t >> 2;                // 0..31 local batch
        int lo4 = t & 3;
        const float* sp =
            state + ((size_t)(zb * 32 + bl) * L0 + l0) * C0 + (ct >> 3);
#pragma unroll
        for (int i = 0; i < 11; i++) {
            int lr = lo4 + 4 * i;
            if (lr < SSPAN) s_st[bl][lr] = sp[(size_t)lr * C0];
        }
    }
    __syncthreads();

    // ---------------- Phase 1b: block1 -> o1s ----------------
    {
        int bp = t >> 3;                 // 0..15 local pair
        const float* se = s_st[2 * bp];
        const float* so = s_st[2 * bp + 1];
        float w1[5];
#pragma unroll
        for (int k = 0; k < 5; k++) w1[k] = k1w[k * CH1 + ct];
        float bias1 = b1[ct];
#pragma unroll
        for (int i = 0; i < 5; i++) {
            int m = (t & 7) + 8 * i;
            if (m < OSPAN) {
                float ve = bias1, vo = bias1;
#pragma unroll
                for (int k = 0; k < 5; k++) {
                    ve = fmaf(se[m + k], w1[k], ve);
                    vo = fmaf(so[m + k], w1[k], vo);
                }
                o1s[bp][m] = pack2(fmaxf(ve, 0.f), fmaxf(vo, 0.f));
            }
        }
    }
    __syncthreads();

    // ---------------- Phase 1c: block2 -> x2 tile ----------------
    {
        int fc  = t & 7;                 // channel in tile
        int fbp = t >> 3;                // batch pair 0..15
        int cF  = ct * 8 + fc;

        ull w2p[5];
#pragma unroll
        for (int k = 0; k < 5; k++) {
            float w = k2w[k * CH2 + cF]; w2p[k] = pack2(w, w);
        }
        float bv = b2[cF];
        ull bias2p = pack2(bv, bv);

        const ull* orow = o1s[fbp];
        ull w[5];
#pragma unroll
        for (int k = 0; k < 5; k++) w[k] = orow[k];
        ull* dst = &x2s[(fbp * 8 + fc) * SPAN_PAD];
#pragma unroll
        for (int i = 0; i < SPAN; i++) {
            ull v = bias2p;
#pragma unroll
            for (int k = 0; k < 5; k++) v = fma2(w[(i + k) % 5], w2p[k], v);
            dst[i] = relu2(v);
            if (i + 1 < SPAN) w[i % 5] = orow[i + 5];
        }
    }
    __syncthreads();

    // ---------------- Phase 2: conv3 + dense (round-8 loop) ----------------
    int cl = t & 7;                      // channel lane
    int fq = (t >> 3) & 3;               // filters fq*2, fq*2+1
    int wg = t >> 5;                     // warp -> pairs wg*4..wg*4+3
    int c  = ct * 8 + cl;

    ull w3p[5][2];
#pragma unroll
    for (int k = 0; k < 5; k++)
#pragma unroll
        for (int j = 0; j < 2; j++) {
            float w = k3w[k * CH3 + c * 8 + fq * 2 + j];
            w3p[k][j] = pack2(w, w);
        }
    ull bias3p[2];
#pragma unroll
    for (int j = 0; j < 2; j++) {
        float bv = b3[c * 8 + fq * 2 + j];
        bias3p[j] = pack2(bv, bv);
    }

    const ulonglong2* xsv[4];
#pragma unroll
    for (int p = 0; p < 4; p++)
        xsv[p] = (const ulonglong2*)&x2s[((wg * 4 + p) * 8 + cl) * SPAN_PAD];

    // W quad (f0c0,f0c1,f1c0,f1c1) at ulonglong2 index l*4096 + c*4 + fq
    const ulonglong2* Wq2 =
        (const ulonglong2*)W + ((size_t)l0 * 4096 + c * 4 + fq);

    ull xw[4][6];
#pragma unroll
    for (int p = 0; p < 4; p++) {
        ulonglong2 a = xsv[p][0], b_ = xsv[p][1], e = xsv[p][2];
        xw[p][0] = a.x; xw[p][1] = a.y; xw[p][2] = b_.x;
        xw[p][3] = b_.y; xw[p][4] = e.x; xw[p][5] = e.y;
    }

    ull accC0[4] = {}, accC1[4] = {};    // packed (b_even, b_odd) per pair

    ulonglong2 u = Wq2[0];
#pragma unroll
    for (int s = 0; s < 14; s++) {
        int i = 2 * s;
        ulonglong2 un1 = Wq2[(size_t)(i + 1) * 4096];
        ulonglong2 rf0 = xsv[0][(i + 6) >> 1];
        ulonglong2 rf1 = xsv[1][(i + 6) >> 1];
        do_l4(i, xw, w3p, bias3p, u.x, u.y, accC0, accC1);
        ulonglong2 un2 = Wq2[(size_t)(i + 2) * 4096];
        ulonglong2 rf2 = xsv[2][(i + 6) >> 1];
        ulonglong2 rf3 = xsv[3][(i + 6) >> 1];
        do_l4(i + 1, xw, w3p, bias3p, un1.x, un1.y, accC0, accC1);
        xw[0][i % 6] = rf0.x; xw[0][(i + 1) % 6] = rf0.y;
        xw[1][i % 6] = rf1.x; xw[1][(i + 1) % 6] = rf1.y;
        xw[2][i % 6] = rf2.x; xw[2][(i + 1) % 6] = rf2.y;
        xw[3][i % 6] = rf3.x; xw[3][(i + 1) % 6] = rf3.y;
        u = un2;
    }
    do_l4(28, xw, w3p, bias3p, u.x, u.y, accC0, accC1);  // final odd l

    // Warp reduction over 32 lanes (8 c x 4 fq) per pair / batch-half / col
    int sl = ct & (NSLICE - 1);
#pragma unroll
    for (int p = 0; p < 4; p++) {
        float se0, so0, se1, so1;
        unpack2(accC0[p], se0, so0);
        unpack2(accC1[p], se1, so1);
#pragma unroll
        for (int s = 16; s > 0; s >>= 1) {
            se0 += __shfl_xor_sync(0xFFFFFFFFu, se0, s);
            so0 += __shfl_xor_sync(0xFFFFFFFFu, so0, s);
            se1 += __shfl_xor_sync(0xFFFFFFFFu, se1, s);
            so1 += __shfl_xor_sync(0xFFFFFFFFu, so1, s);
        }
        if ((t & 31) == 0) {
            int be = (zb * 16 + wg * 4 + p) * 2;   // even batch of this pair
            atomicAdd(&g_acc[sl][be * 2],     se0);
            atomicAdd(&g_acc[sl][be * 2 + 1], se1);
            atomicAdd(&g_acc[sl][be * 2 + 2], so0);
            atomicAdd(&g_acc[sl][be * 2 + 3], so1);
        }
    }

    // Last block finalizes (threadfence reduction pattern), then self-restores
    // g_acc/g_count to zero so the next graph replay starts clean.
    __shared__ bool s_last;
    __threadfence();
    __syncthreads();
    if (t == 0) s_last = (atomicAdd(&g_count, 1u) == FUSED_BLOCKS - 1u);
    __syncthreads();
    if (s_last) {
        __threadfence();
        int i = t;  // 128 threads == 128 outputs
        volatile float* ga = (volatile float*)g_acc;
        float v = 0.f;
#pragma unroll
        for (int s = 0; s < NSLICE; s++) v += ga[s * BB * 2 + i];
        out[i] = tanhf(v + bd[i & 1]);
        // Self-restore: thread i zeros exactly the entries it just read.
#pragma unroll
        for (int s = 0; s < NSLICE; s++) ga[s * BB * 2 + i] = 0.f;
        if (t == 0) g_count = 0u;
    }
}

// ---------------------------------------------------------------------------
extern "C" void kernel_launch(void* const* d_in, const int* in_sizes, int n_in,
                              void* d_out, int out_size) {
    const float* state = (const float*)d_in[0];
    const float* k1w   = (const float*)d_in[1];
    const float* b1    = (const float*)d_in[2];
    const float* k2w   = (const float*)d_in[3];
    const float* b2    = (const float*)d_in[4];
    const float* k3w   = (const float*)d_in[5];
    const float* b3    = (const float*)d_in[6];
    const float* W     = (const float*)d_in[7];
    const float* bd    = (const float*)d_in[8];
    float* out = (float*)d_out;

    fused_all_kernel<<<dim3(CTILES, NLC, ZB), 128>>>(
        state, k1w, b1, k2w, b2, k3w, b3, W, bd, out);
}